// round 1
// baseline (speedup 1.0000x reference)
#include <cuda_runtime.h>
#include <cstddef>

#define N_NODES 100000
#define N_EDGES 600000
#define D 128
#define BN_EPS 1e-5f

// ---------------- scratch (static device globals; no allocation) ----------------
__device__ float  g_acc_o[(size_t)N_NODES * D];   // sum of (h_src - e) at dst
__device__ float  g_acc_i[(size_t)N_NODES * D];   // sum of (h_dst - e) at src
__device__ float  g_cnt[2 * N_NODES];             // [0:N) in-deg(dst), [N:2N) deg at src
__device__ float  g_W[384 * D];                   // packed W^T: [k][j], k = 0..383
__device__ float  g_bias[D];                      // b_O + b_I + b_S
__device__ double g_sum[D];
__device__ double g_sumsq[D];
__device__ float  g_scale[D];
__device__ float  g_shift[D];

// ---------------- helpers ----------------
__device__ __forceinline__ void red_add_v4(float* p, float4 v) {
    asm volatile("red.global.add.v4.f32 [%0], {%1,%2,%3,%4};"
                 :: "l"(p), "f"(v.x), "f"(v.y), "f"(v.z), "f"(v.w) : "memory");
}

// ---------------- K0: zero scratch ----------------
__global__ void k_zero() {
    size_t idx = (size_t)blockIdx.x * blockDim.x + threadIdx.x;
    size_t stride = (size_t)gridDim.x * blockDim.x;
    const size_t n4 = (size_t)N_NODES * D / 4;
    float4 z = make_float4(0.f, 0.f, 0.f, 0.f);
    float4* ao = reinterpret_cast<float4*>(g_acc_o);
    float4* ai = reinterpret_cast<float4*>(g_acc_i);
    for (size_t i = idx; i < n4; i += stride) { ao[i] = z; ai[i] = z; }
    float4* cp = reinterpret_cast<float4*>(g_cnt);
    for (size_t i = idx; i < (2 * N_NODES) / 4; i += stride) cp[i] = z;
    if (idx < D) { g_sum[idx] = 0.0; g_sumsq[idx] = 0.0; }
}

// ---------------- K1: pack W^T and combined bias ----------------
__global__ void k_pack(const float* __restrict__ WO, const float* __restrict__ WI,
                       const float* __restrict__ WS, const float* __restrict__ bO,
                       const float* __restrict__ bI, const float* __restrict__ bS) {
    int idx = blockIdx.x * blockDim.x + threadIdx.x;
    int stride = gridDim.x * blockDim.x;
    for (int i = idx; i < 384 * D; i += stride) {
        int k = i / D, j = i % D;
        float v;
        if (k < 128)      v = WO[j * D + k];
        else if (k < 256) v = WI[j * D + (k - 128)];
        else              v = WS[j * D + (k - 256)];
        g_W[i] = v;
    }
    if (idx < D) g_bias[idx] = bO[idx] + bI[idx] + bS[idx];
}

// ---------------- K2: edge scatter (one warp per edge) ----------------
__global__ __launch_bounds__(256) void k_scatter(const float* __restrict__ node,
                                                 const float* __restrict__ edge,
                                                 const int* __restrict__ src,
                                                 const int* __restrict__ dst) {
    int e = blockIdx.x * 8 + (threadIdx.x >> 5);
    if (e >= N_EDGES) return;
    int lane = threadIdx.x & 31;
    int s = __ldg(&src[e]);
    int d = __ldg(&dst[e]);
    const float4* e4 = reinterpret_cast<const float4*>(edge);
    const float4* n4 = reinterpret_cast<const float4*>(node);
    float4 ee = __ldg(&e4[(size_t)e * 32 + lane]);
    float4 ns = __ldg(&n4[(size_t)s * 32 + lane]);
    float4 nd = __ldg(&n4[(size_t)d * 32 + lane]);
    float4 mo = make_float4(ns.x - ee.x, ns.y - ee.y, ns.z - ee.z, ns.w - ee.w);
    float4 mi = make_float4(nd.x - ee.x, nd.y - ee.y, nd.z - ee.z, nd.w - ee.w);
    red_add_v4(g_acc_o + (size_t)d * D + lane * 4, mo);
    red_add_v4(g_acc_i + (size_t)s * D + lane * 4, mi);
    if (lane == 0) {
        atomicAdd(&g_cnt[d], 1.f);
        atomicAdd(&g_cnt[N_NODES + s], 1.f);
    }
}

// ---------------- K3: fused projections + bias + /3 + BN partial stats ----------------
// Block: 256 threads = 32 (tx: 4 output cols each) x 8 (ty: 4 rows each) -> 32 rows/block.
#define RT 32
#define KC 64
#define ROW_STRIDE 385   // 384 + 1 pad: ty offsets hit distinct banks
#define SMEM_BYTES (RT * ROW_STRIDE * 4 + KC * 128 * 4)

__global__ __launch_bounds__(256) void k_gemm(const float* __restrict__ node,
                                              float* __restrict__ out) {
    extern __shared__ float sm[];
    float* s_rows = sm;                      // RT x ROW_STRIDE
    float* s_w    = sm + RT * ROW_STRIDE;    // KC x 128
    __shared__ float inv_o[RT], inv_i[RT];

    int tid = threadIdx.x;
    int tx = tid & 31, ty = tid >> 5;
    int row0 = blockIdx.x * RT;

    if (tid < RT)           inv_o[tid]      = 1.f / fmaxf(g_cnt[row0 + tid], 1.f);
    else if (tid < 2 * RT)  inv_i[tid - RT] = 1.f / fmaxf(g_cnt[N_NODES + row0 + tid - RT], 1.f);
    __syncthreads();

    // stage 32 rows of [ho | hi | x] (384 each)
    for (int idx = tid; idx < RT * 384; idx += 256) {
        int r = idx / 384, c = idx % 384;
        size_t i = (size_t)(row0 + r);
        float v;
        if (c < 128)      v = g_acc_o[i * D + c] * inv_o[r];
        else if (c < 256) v = g_acc_i[i * D + (c - 128)] * inv_i[r];
        else              v = __ldg(&node[i * D + (c - 256)]);
        s_rows[r * ROW_STRIDE + c] = v;
    }

    float acc[4][4];
#pragma unroll
    for (int r = 0; r < 4; r++)
#pragma unroll
        for (int c = 0; c < 4; c++) acc[r][c] = 0.f;

    for (int kc = 0; kc < 384; kc += KC) {
        __syncthreads();
        const float4* gw4 = reinterpret_cast<const float4*>(g_W) + kc * 32;
        float4* sw4 = reinterpret_cast<float4*>(s_w);
        for (int idx = tid; idx < KC * 32; idx += 256) sw4[idx] = __ldg(&gw4[idx]);
        __syncthreads();
#pragma unroll 8
        for (int kk = 0; kk < KC; kk++) {
            float4 w = reinterpret_cast<float4*>(s_w)[kk * 32 + tx];
#pragma unroll
            for (int r = 0; r < 4; r++) {
                float sv = s_rows[(ty * 4 + r) * ROW_STRIDE + kc + kk];
                acc[r][0] = fmaf(sv, w.x, acc[r][0]);
                acc[r][1] = fmaf(sv, w.y, acc[r][1]);
                acc[r][2] = fmaf(sv, w.z, acc[r][2]);
                acc[r][3] = fmaf(sv, w.w, acc[r][3]);
            }
        }
    }

    // epilogue: h = (acc + bias)/3, store, accumulate BN partials
    float4 bv = reinterpret_cast<const float4*>(g_bias)[tx];
    float ps[4] = {0, 0, 0, 0}, pq[4] = {0, 0, 0, 0};
    const float third = 1.f / 3.f;
#pragma unroll
    for (int r = 0; r < 4; r++) {
        size_t i = (size_t)(row0 + ty * 4 + r);
        float4 h;
        h.x = (acc[r][0] + bv.x) * third;
        h.y = (acc[r][1] + bv.y) * third;
        h.z = (acc[r][2] + bv.z) * third;
        h.w = (acc[r][3] + bv.w) * third;
        reinterpret_cast<float4*>(out)[i * 32 + tx] = h;
        ps[0] += h.x; pq[0] += h.x * h.x;
        ps[1] += h.y; pq[1] += h.y * h.y;
        ps[2] += h.z; pq[2] += h.z * h.z;
        ps[3] += h.w; pq[3] += h.w * h.w;
    }
    __syncthreads();
    float* s_ps = s_w;          // 8 x 128
    float* s_pq = s_w + 1024;   // 8 x 128
#pragma unroll
    for (int c = 0; c < 4; c++) {
        s_ps[ty * 128 + tx * 4 + c] = ps[c];
        s_pq[ty * 128 + tx * 4 + c] = pq[c];
    }
    __syncthreads();
    if (tid < 128) {
        float S = 0.f, Q = 0.f;
#pragma unroll
        for (int t = 0; t < 8; t++) { S += s_ps[t * 128 + tid]; Q += s_pq[t * 128 + tid]; }
        atomicAdd(&g_sum[tid], (double)S);
        atomicAdd(&g_sumsq[tid], (double)Q);
    }
}

// ---------------- K4: finalize BN affine ----------------
__global__ void k_finalize(const float* __restrict__ gamma, const float* __restrict__ beta) {
    int j = threadIdx.x;
    double mu = g_sum[j] / (double)N_NODES;
    double var = g_sumsq[j] / (double)N_NODES - mu * mu;
    float sc = gamma[j] * rsqrtf((float)var + BN_EPS);
    g_scale[j] = sc;
    g_shift[j] = beta[j] - (float)mu * sc;
}

// ---------------- K5: in-place normalize ----------------
__global__ void k_bn(float* __restrict__ out) {
    size_t idx = (size_t)blockIdx.x * blockDim.x + threadIdx.x;
    size_t stride = (size_t)gridDim.x * blockDim.x;
    const size_t n4 = (size_t)N_NODES * D / 4;
    float4* o4 = reinterpret_cast<float4*>(out);
    const float4* sc4 = reinterpret_cast<const float4*>(g_scale);
    const float4* sh4 = reinterpret_cast<const float4*>(g_shift);
    for (size_t i = idx; i < n4; i += stride) {
        float4 sc = sc4[i & 31];
        float4 sh = sh4[i & 31];
        float4 v = o4[i];
        v.x = fmaf(v.x, sc.x, sh.x);
        v.y = fmaf(v.y, sc.y, sh.y);
        v.z = fmaf(v.z, sc.z, sh.z);
        v.w = fmaf(v.w, sc.w, sh.w);
        o4[i] = v;
    }
}

// ---------------- launch ----------------
extern "C" void kernel_launch(void* const* d_in, const int* in_sizes, int n_in,
                              void* d_out, int out_size) {
    const float* node  = (const float*)d_in[0];
    const float* edge  = (const float*)d_in[1];
    const float* WO    = (const float*)d_in[2];
    const float* bO    = (const float*)d_in[3];
    const float* WI    = (const float*)d_in[4];
    const float* bI    = (const float*)d_in[5];
    const float* WS    = (const float*)d_in[6];
    const float* bS    = (const float*)d_in[7];
    const float* gamma = (const float*)d_in[8];
    const float* beta  = (const float*)d_in[9];
    const int*   src   = (const int*)d_in[10];
    const int*   dst   = (const int*)d_in[11];
    float* out = (float*)d_out;

    cudaFuncSetAttribute(k_gemm, cudaFuncAttributeMaxDynamicSharedMemorySize, SMEM_BYTES);

    k_zero<<<1184, 256>>>();
    k_pack<<<256, 256>>>(WO, WI, WS, bO, bI, bS);
    k_scatter<<<N_EDGES / 8, 256>>>(node, edge, src, dst);
    k_gemm<<<N_NODES / RT, 256, SMEM_BYTES>>>(node, out);
    k_finalize<<<1, 128>>>(gamma, beta);
    k_bn<<<2048, 256>>>(out);
}

// round 2
// speedup vs baseline: 1.4246x; 1.4246x over previous
#include <cuda_runtime.h>
#include <cstddef>

#define N_NODES 100000
#define N_EDGES 600000
#define D 128
#define BN_EPS 1e-5f

// ---------------- scratch (static device globals; no allocation) ----------------
__device__ float  g_acc_o[(size_t)N_NODES * D];   // sum of (h_src - e) at dst
__device__ float  g_acc_i[(size_t)N_NODES * D];   // sum of (h_dst - e) at src
__device__ float  g_cnt[2 * N_NODES];             // [0:N) in-deg(dst), [N:2N) deg at src
__device__ float  g_W[384 * D];                   // packed W^T: [k][j], k = 0..383
__device__ float  g_bias[D];                      // b_O + b_I + b_S
__device__ double g_sum[D];
__device__ double g_sumsq[D];
__device__ float  g_scale[D];
__device__ float  g_shift[D];

// ---------------- helpers ----------------
__device__ __forceinline__ void red_add_v4(float* p, float4 v) {
    asm volatile("red.global.add.v4.f32 [%0], {%1,%2,%3,%4};"
                 :: "l"(p), "f"(v.x), "f"(v.y), "f"(v.z), "f"(v.w) : "memory");
}

// ---------------- K0: zero scratch ----------------
__global__ void k_zero() {
    size_t idx = (size_t)blockIdx.x * blockDim.x + threadIdx.x;
    size_t stride = (size_t)gridDim.x * blockDim.x;
    const size_t n4 = (size_t)N_NODES * D / 4;
    float4 z = make_float4(0.f, 0.f, 0.f, 0.f);
    float4* ao = reinterpret_cast<float4*>(g_acc_o);
    float4* ai = reinterpret_cast<float4*>(g_acc_i);
    for (size_t i = idx; i < n4; i += stride) { ao[i] = z; ai[i] = z; }
    float4* cp = reinterpret_cast<float4*>(g_cnt);
    for (size_t i = idx; i < (2 * N_NODES) / 4; i += stride) cp[i] = z;
    if (idx < D) { g_sum[idx] = 0.0; g_sumsq[idx] = 0.0; }
}

// ---------------- K1: pack W^T and combined bias ----------------
__global__ void k_pack(const float* __restrict__ WO, const float* __restrict__ WI,
                       const float* __restrict__ WS, const float* __restrict__ bO,
                       const float* __restrict__ bI, const float* __restrict__ bS) {
    int idx = blockIdx.x * blockDim.x + threadIdx.x;
    int stride = gridDim.x * blockDim.x;
    for (int i = idx; i < 384 * D; i += stride) {
        int k = i / D, j = i % D;
        float v;
        if (k < 128)      v = WO[j * D + k];
        else if (k < 256) v = WI[j * D + (k - 128)];
        else              v = WS[j * D + (k - 256)];
        g_W[i] = v;
    }
    if (idx < D) g_bias[idx] = bO[idx] + bI[idx] + bS[idx];
}

// ---------------- K2: edge scatter (one warp per edge) ----------------
__global__ __launch_bounds__(256) void k_scatter(const float* __restrict__ node,
                                                 const float* __restrict__ edge,
                                                 const int* __restrict__ src,
                                                 const int* __restrict__ dst) {
    int e = blockIdx.x * 8 + (threadIdx.x >> 5);
    if (e >= N_EDGES) return;
    int lane = threadIdx.x & 31;
    int s = __ldg(&src[e]);
    int d = __ldg(&dst[e]);
    const float4* e4 = reinterpret_cast<const float4*>(edge);
    const float4* n4 = reinterpret_cast<const float4*>(node);
    float4 ee = __ldg(&e4[(size_t)e * 32 + lane]);
    float4 ns = __ldg(&n4[(size_t)s * 32 + lane]);
    float4 nd = __ldg(&n4[(size_t)d * 32 + lane]);
    float4 mo = make_float4(ns.x - ee.x, ns.y - ee.y, ns.z - ee.z, ns.w - ee.w);
    float4 mi = make_float4(nd.x - ee.x, nd.y - ee.y, nd.z - ee.z, nd.w - ee.w);
    red_add_v4(g_acc_o + (size_t)d * D + lane * 4, mo);
    red_add_v4(g_acc_i + (size_t)s * D + lane * 4, mi);
    if (lane == 0) {
        atomicAdd(&g_cnt[d], 1.f);
        atomicAdd(&g_cnt[N_NODES + s], 1.f);
    }
}

// ---------------- K3: fused GEMM + bias + /3 + BN partial stats ----------------
// C[100000 x 128] = A[100000 x 384] * W[384 x 128], A built on the fly.
// BM=64 BN=128 BK=32, 256 threads, thread tile 8x4.
#define BM 64
#define BN 128
#define BK 32
#define NCHUNK 12

__global__ __launch_bounds__(256) void k_gemm(const float* __restrict__ node,
                                              float* __restrict__ out) {
    __shared__ float sa[BK * BM];      // A tile transposed: [k][m]
    __shared__ float sw[BK * BN];      // W tile: [k][n]
    __shared__ float s_invo[BM], s_invi[BM];

    int tid = threadIdx.x;
    int tx = tid & 31;        // output col group: cols tx*4 .. tx*4+3
    int wp = tid >> 5;        // warp id: rows wp*8 .. wp*8+7
    int row0 = blockIdx.x * BM;

    if (tid < BM) {
        int r = row0 + tid;
        s_invo[tid] = (r < N_NODES) ? 1.f / fmaxf(g_cnt[r], 1.f) : 0.f;
    } else if (tid < 2 * BM) {
        int r = row0 + tid - BM;
        s_invi[tid - BM] = (r < N_NODES) ? 1.f / fmaxf(g_cnt[N_NODES + r], 1.f) : 0.f;
    }

    float acc[8][4];
#pragma unroll
    for (int r = 0; r < 8; r++)
#pragma unroll
        for (int c = 0; c < 4; c++) acc[r][c] = 0.f;

    const float4* no4 = reinterpret_cast<const float4*>(node);
    const float4* ao4 = reinterpret_cast<const float4*>(g_acc_o);
    const float4* ai4 = reinterpret_cast<const float4*>(g_acc_i);
    const float4* wg4 = reinterpret_cast<const float4*>(g_W);
    float4* sw4 = reinterpret_cast<float4*>(sw);

    __syncthreads();   // inv tables ready

    for (int c = 0; c < NCHUNK; c++) {
        int kc = c * BK;
        int sel = kc >> 7;           // 0: acc_o, 1: acc_i, 2: node
        int cb4 = (kc & 127) >> 2;   // float4 column base within source

        // --- stage A tile (64 rows x 32 k) transposed into sa[k][m] ---
#pragma unroll
        for (int t = 0; t < 2; t++) {
            int id = tid + t * 256;          // 0..511
            int m = id & 63;
            int kq = id >> 6;                // float4 index within chunk, 0..7
            int r = row0 + m;
            float4 v = make_float4(0.f, 0.f, 0.f, 0.f);
            if (r < N_NODES) {
                size_t off = (size_t)r * 32 + cb4 + kq;
                if (sel == 0) {
                    v = __ldg(&ao4[off]);
                    float s = s_invo[m];
                    v.x *= s; v.y *= s; v.z *= s; v.w *= s;
                } else if (sel == 1) {
                    v = __ldg(&ai4[off]);
                    float s = s_invi[m];
                    v.x *= s; v.y *= s; v.z *= s; v.w *= s;
                } else {
                    v = __ldg(&no4[off]);
                }
            }
            int kb = kq * 4;
            sa[(kb + 0) * BM + m] = v.x;
            sa[(kb + 1) * BM + m] = v.y;
            sa[(kb + 2) * BM + m] = v.z;
            sa[(kb + 3) * BM + m] = v.w;
        }

        // --- stage W tile (32 x 128) ---
#pragma unroll
        for (int t = 0; t < 4; t++) {
            int id = tid + t * 256;          // 0..1023 float4s
            sw4[id] = __ldg(&wg4[kc * 32 + id]);
        }
        __syncthreads();

        // --- compute ---
#pragma unroll 8
        for (int kk = 0; kk < BK; kk++) {
            float4 w = sw4[kk * 32 + tx];
            const float4* sap = reinterpret_cast<const float4*>(sa) + ((kk * BM + wp * 8) >> 2);
            float4 a0 = sap[0];
            float4 a1 = sap[1];
            float av[8] = {a0.x, a0.y, a0.z, a0.w, a1.x, a1.y, a1.z, a1.w};
#pragma unroll
            for (int r = 0; r < 8; r++) {
                acc[r][0] = fmaf(av[r], w.x, acc[r][0]);
                acc[r][1] = fmaf(av[r], w.y, acc[r][1]);
                acc[r][2] = fmaf(av[r], w.z, acc[r][2]);
                acc[r][3] = fmaf(av[r], w.w, acc[r][3]);
            }
        }
        __syncthreads();
    }

    // --- epilogue: h = (acc + bias)/3, store, BN partials ---
    float4 bv = reinterpret_cast<const float4*>(g_bias)[tx];
    float ps[4] = {0, 0, 0, 0}, pq[4] = {0, 0, 0, 0};
    const float third = 1.f / 3.f;
#pragma unroll
    for (int r = 0; r < 8; r++) {
        int row = row0 + wp * 8 + r;
        if (row < N_NODES) {
            float4 h;
            h.x = (acc[r][0] + bv.x) * third;
            h.y = (acc[r][1] + bv.y) * third;
            h.z = (acc[r][2] + bv.z) * third;
            h.w = (acc[r][3] + bv.w) * third;
            reinterpret_cast<float4*>(out)[(size_t)row * 32 + tx] = h;
            ps[0] += h.x; pq[0] += h.x * h.x;
            ps[1] += h.y; pq[1] += h.y * h.y;
            ps[2] += h.z; pq[2] += h.z * h.z;
            ps[3] += h.w; pq[3] += h.w * h.w;
        }
    }
    __syncthreads();   // done reading sw; reuse as reduction scratch
    float* s_ps = sw;           // 8 x 128
    float* s_pq = sw + 1024;    // 8 x 128
#pragma unroll
    for (int cc = 0; cc < 4; cc++) {
        s_ps[wp * 128 + tx * 4 + cc] = ps[cc];
        s_pq[wp * 128 + tx * 4 + cc] = pq[cc];
    }
    __syncthreads();
    if (tid < 128) {
        float S = 0.f, Q = 0.f;
#pragma unroll
        for (int t = 0; t < 8; t++) { S += s_ps[t * 128 + tid]; Q += s_pq[t * 128 + tid]; }
        atomicAdd(&g_sum[tid], (double)S);
        atomicAdd(&g_sumsq[tid], (double)Q);
    }
}

// ---------------- K4: finalize BN affine ----------------
__global__ void k_finalize(const float* __restrict__ gamma, const float* __restrict__ beta) {
    int j = threadIdx.x;
    double mu = g_sum[j] / (double)N_NODES;
    double var = g_sumsq[j] / (double)N_NODES - mu * mu;
    float sc = gamma[j] * rsqrtf((float)var + BN_EPS);
    g_scale[j] = sc;
    g_shift[j] = beta[j] - (float)mu * sc;
}

// ---------------- K5: in-place normalize ----------------
__global__ void k_bn(float* __restrict__ out) {
    size_t idx = (size_t)blockIdx.x * blockDim.x + threadIdx.x;
    size_t stride = (size_t)gridDim.x * blockDim.x;
    const size_t n4 = (size_t)N_NODES * D / 4;
    float4* o4 = reinterpret_cast<float4*>(out);
    const float4* sc4 = reinterpret_cast<const float4*>(g_scale);
    const float4* sh4 = reinterpret_cast<const float4*>(g_shift);
    for (size_t i = idx; i < n4; i += stride) {
        float4 sc = sc4[i & 31];
        float4 sh = sh4[i & 31];
        float4 v = o4[i];
        v.x = fmaf(v.x, sc.x, sh.x);
        v.y = fmaf(v.y, sc.y, sh.y);
        v.z = fmaf(v.z, sc.z, sh.z);
        v.w = fmaf(v.w, sc.w, sh.w);
        o4[i] = v;
    }
}

// ---------------- launch ----------------
extern "C" void kernel_launch(void* const* d_in, const int* in_sizes, int n_in,
                              void* d_out, int out_size) {
    const float* node  = (const float*)d_in[0];
    const float* edge  = (const float*)d_in[1];
    const float* WO    = (const float*)d_in[2];
    const float* bO    = (const float*)d_in[3];
    const float* WI    = (const float*)d_in[4];
    const float* bI    = (const float*)d_in[5];
    const float* WS    = (const float*)d_in[6];
    const float* bS    = (const float*)d_in[7];
    const float* gamma = (const float*)d_in[8];
    const float* beta  = (const float*)d_in[9];
    const int*   src   = (const int*)d_in[10];
    const int*   dst   = (const int*)d_in[11];
    float* out = (float*)d_out;

    k_zero<<<1184, 256>>>();
    k_pack<<<256, 256>>>(WO, WI, WS, bO, bI, bS);
    k_scatter<<<N_EDGES / 8, 256>>>(node, edge, src, dst);
    k_gemm<<<(N_NODES + BM - 1) / BM, 256>>>(node, out);
    k_finalize<<<1, 128>>>(gamma, beta);
    k_bn<<<2048, 256>>>(out);
}

// round 4
// speedup vs baseline: 1.9281x; 1.3535x over previous
#include <cuda_runtime.h>
#include <cuda_bf16.h>
#include <cstdint>
#include <cstddef>

#define N_NODES 100000
#define N_EDGES 600000
#define D 128
#define BN_EPS 1e-5f

// ---------------- scratch (static device globals; no allocation) ----------------
__device__ float  g_acc_o[(size_t)N_NODES * D];   // sum of (h_src - e) at dst
__device__ float  g_acc_i[(size_t)N_NODES * D];   // sum of (h_dst - e) at src
__device__ float  g_cnt[2 * N_NODES];             // [0:N) in-deg(dst), [N:2N) deg at src
// B fragments in mma order: [kstep 0..23][ntile 0..15][lane 0..31] = (b0h,b1h,b0l,b1l)
__device__ uint4  g_Bfrag[24 * 16 * 32];
__device__ float  g_bias[D];                      // b_O + b_I + b_S
__device__ double g_sum[D];
__device__ double g_sumsq[D];
__device__ float  g_scale[D];
__device__ float  g_shift[D];

// ---------------- helpers ----------------
__device__ __forceinline__ void red_add_v4(float* p, float4 v) {
    asm volatile("red.global.add.v4.f32 [%0], {%1,%2,%3,%4};"
                 :: "l"(p), "f"(v.x), "f"(v.y), "f"(v.z), "f"(v.w) : "memory");
}

__device__ __forceinline__ void mma16816(float* d, uint32_t a0, uint32_t a1, uint32_t a2,
                                         uint32_t a3, uint32_t b0, uint32_t b1) {
    asm volatile(
        "mma.sync.aligned.m16n8k16.row.col.f32.bf16.bf16.f32 "
        "{%0,%1,%2,%3}, {%4,%5,%6,%7}, {%8,%9}, {%0,%1,%2,%3};"
        : "+f"(d[0]), "+f"(d[1]), "+f"(d[2]), "+f"(d[3])
        : "r"(a0), "r"(a1), "r"(a2), "r"(a3), "r"(b0), "r"(b1));
}

// split scaled float2 into bf16x2 hi and lo words (x -> low half, y -> high half)
__device__ __forceinline__ void split2(float2 v, float s, uint32_t& h, uint32_t& l) {
    float x = v.x * s, y = v.y * s;
    __nv_bfloat162 hp = __floats2bfloat162_rn(x, y);
    float hx = __low2float(hp), hy = __high2float(hp);
    __nv_bfloat162 lp = __floats2bfloat162_rn(x - hx, y - hy);
    h = *reinterpret_cast<uint32_t*>(&hp);
    l = *reinterpret_cast<uint32_t*>(&lp);
}

// ---------------- K0: zero scratch ----------------
__global__ void k_zero() {
    size_t idx = (size_t)blockIdx.x * blockDim.x + threadIdx.x;
    size_t stride = (size_t)gridDim.x * blockDim.x;
    const size_t n4 = (size_t)N_NODES * D / 4;
    float4 z = make_float4(0.f, 0.f, 0.f, 0.f);
    float4* ao = reinterpret_cast<float4*>(g_acc_o);
    float4* ai = reinterpret_cast<float4*>(g_acc_i);
    for (size_t i = idx; i < n4; i += stride) { ao[i] = z; ai[i] = z; }
    float4* cp = reinterpret_cast<float4*>(g_cnt);
    for (size_t i = idx; i < (2 * N_NODES) / 4; i += stride) cp[i] = z;
    if (idx < D) { g_sum[idx] = 0.0; g_sumsq[idx] = 0.0; }
}

// ---------------- K1: pack W into bf16 hi/lo mma B-fragments + combined bias ----------------
__global__ void k_pack(const float* __restrict__ WO, const float* __restrict__ WI,
                       const float* __restrict__ WS, const float* __restrict__ bO,
                       const float* __restrict__ bI, const float* __restrict__ bS) {
    int idx = blockIdx.x * blockDim.x + threadIdx.x;
    if (idx < 24 * 16 * 32) {
        int t  = idx >> 9;          // kstep 0..23
        int nt = (idx >> 5) & 15;   // ntile 0..15
        int l  = idx & 31;          // lane
        int n  = nt * 8 + (l >> 2);           // output col
        int kg = t * 16 + (l & 3) * 2;        // global k of b0 first element
        const float* Wsrc = (kg < 128) ? WO : ((kg < 256) ? WI : WS);
        int kk = kg & 127;
        float w00 = __ldg(&Wsrc[n * 128 + kk]);
        float w01 = __ldg(&Wsrc[n * 128 + kk + 1]);
        float w10 = __ldg(&Wsrc[n * 128 + kk + 8]);
        float w11 = __ldg(&Wsrc[n * 128 + kk + 9]);
        uint32_t b0h, b0l, b1h, b1l;
        split2(make_float2(w00, w01), 1.f, b0h, b0l);
        split2(make_float2(w10, w11), 1.f, b1h, b1l);
        g_Bfrag[idx] = make_uint4(b0h, b1h, b0l, b1l);
    }
    if (idx < D) g_bias[idx] = bO[idx] + bI[idx] + bS[idx];
}

// ---------------- K2: edge scatter (one warp per edge) ----------------
__global__ __launch_bounds__(256) void k_scatter(const float* __restrict__ node,
                                                 const float* __restrict__ edge,
                                                 const int* __restrict__ src,
                                                 const int* __restrict__ dst) {
    int e = blockIdx.x * 8 + (threadIdx.x >> 5);
    if (e >= N_EDGES) return;
    int lane = threadIdx.x & 31;
    int s = __ldg(&src[e]);
    int d = __ldg(&dst[e]);
    const float4* e4 = reinterpret_cast<const float4*>(edge);
    const float4* n4 = reinterpret_cast<const float4*>(node);
    float4 ee = __ldg(&e4[(size_t)e * 32 + lane]);
    float4 ns = __ldg(&n4[(size_t)s * 32 + lane]);
    float4 nd = __ldg(&n4[(size_t)d * 32 + lane]);
    float4 mo = make_float4(ns.x - ee.x, ns.y - ee.y, ns.z - ee.z, ns.w - ee.w);
    float4 mi = make_float4(nd.x - ee.x, nd.y - ee.y, nd.z - ee.z, nd.w - ee.w);
    red_add_v4(g_acc_o + (size_t)d * D + lane * 4, mo);
    red_add_v4(g_acc_i + (size_t)s * D + lane * 4, mi);
    if (lane == 0) {
        atomicAdd(&g_cnt[d], 1.f);
        atomicAdd(&g_cnt[N_NODES + s], 1.f);
    }
}

// ---------------- K3: bf16-split HMMA GEMM ----------------
// CTA: 128 rows x 128 cols, 8 warps = 4 (rows) x 2 (cols), warp tile 32x64.
// A[100000 x 384] built on the fly from {acc_o*inv, acc_i*inv, node} as bf16 hi/lo fragments.
__global__ __launch_bounds__(256, 2) void k_gemm(const float* __restrict__ node,
                                                 float* __restrict__ out) {
    __shared__ float s_inv[2 * 128];

    int tid = threadIdx.x;
    int l = tid & 31;
    int w = tid >> 5;
    int wy = w & 3;           // row group
    int wx = w >> 2;          // col group
    int row0 = blockIdx.x * 128;

    // inverse-degree tables for this CTA's 128 rows
    {
        int i = tid & 127;
        int r = row0 + i;
        float v = 0.f;
        if (r < N_NODES) v = 1.f / fmaxf(g_cnt[(tid < 128 ? 0 : N_NODES) + r], 1.f);
        s_inv[tid] = v;
    }
    __syncthreads();

    float acc[2][8][4];
#pragma unroll
    for (int mt = 0; mt < 2; mt++)
#pragma unroll
        for (int nt = 0; nt < 8; nt++)
#pragma unroll
            for (int q = 0; q < 4; q++) acc[mt][nt][q] = 0.f;

    const int lq = l >> 2;            // 0..7 row-within-tile group
    const int lk = (l & 3) * 2;       // k pair base within kstep

#pragma unroll 2
    for (int t = 0; t < 24; t++) {
        int k0 = t * 16;
        int sel = k0 >> 7;
        int kk = (k0 & 127) + lk;     // column pair base within source, + 8 for second

        uint32_t aH[2][4], aL[2][4];
#pragma unroll
        for (int mt = 0; mt < 2; mt++) {
            int rl0 = wy * 32 + mt * 16 + lq;     // local rows
            int rl1 = rl0 + 8;
            int g0 = row0 + rl0, g1 = row0 + rl1;
            const float* base;
            float s0, s1;
            if (sel == 0)      { base = g_acc_o; s0 = s_inv[rl0];       s1 = s_inv[rl1]; }
            else if (sel == 1) { base = g_acc_i; s0 = s_inv[128 + rl0]; s1 = s_inv[128 + rl1]; }
            else               { base = node;    s0 = 1.f;              s1 = 1.f; }
            const float2* b2 = reinterpret_cast<const float2*>(base);
            float2 zz = make_float2(0.f, 0.f);
            float2 p00 = (g0 < N_NODES) ? __ldg(&b2[(size_t)g0 * 64 + (kk >> 1)]) : zz;
            float2 p01 = (g0 < N_NODES) ? __ldg(&b2[(size_t)g0 * 64 + (kk >> 1) + 4]) : zz;
            float2 p10 = (g1 < N_NODES) ? __ldg(&b2[(size_t)g1 * 64 + (kk >> 1)]) : zz;
            float2 p11 = (g1 < N_NODES) ? __ldg(&b2[(size_t)g1 * 64 + (kk >> 1) + 4]) : zz;
            split2(p00, s0, aH[mt][0], aL[mt][0]);
            split2(p10, s1, aH[mt][1], aL[mt][1]);
            split2(p01, s0, aH[mt][2], aL[mt][2]);
            split2(p11, s1, aH[mt][3], aL[mt][3]);
        }

#pragma unroll
        for (int nt = 0; nt < 8; nt++) {
            uint4 B = __ldg(&g_Bfrag[((t * 16) + (wx * 8 + nt)) * 32 + l]);
#pragma unroll
            for (int mt = 0; mt < 2; mt++) {
                mma16816(acc[mt][nt], aH[mt][0], aH[mt][1], aH[mt][2], aH[mt][3], B.x, B.y);
                mma16816(acc[mt][nt], aH[mt][0], aH[mt][1], aH[mt][2], aH[mt][3], B.z, B.w);
                mma16816(acc[mt][nt], aL[mt][0], aL[mt][1], aL[mt][2], aL[mt][3], B.x, B.y);
            }
        }
    }

    // ---- epilogue: h = (acc + bias)/3 ----
    const float third = 1.f / 3.f;
    const float2* bias2 = reinterpret_cast<const float2*>(g_bias);
    float2* o2 = reinterpret_cast<float2*>(out);
#pragma unroll
    for (int mt = 0; mt < 2; mt++) {
        int ra = row0 + wy * 32 + mt * 16 + lq;
        int rb = ra + 8;
#pragma unroll
        for (int nt = 0; nt < 8; nt++) {
            int col = wx * 64 + nt * 8 + lk;
            float2 bv = __ldg(&bias2[col >> 1]);
            if (ra < N_NODES) {
                float2 h0;
                h0.x = (acc[mt][nt][0] + bv.x) * third;
                h0.y = (acc[mt][nt][1] + bv.y) * third;
                o2[(size_t)ra * 64 + (col >> 1)] = h0;
            }
            if (rb < N_NODES) {
                float2 h1;
                h1.x = (acc[mt][nt][2] + bv.x) * third;
                h1.y = (acc[mt][nt][3] + bv.y) * third;
                o2[(size_t)rb * 64 + (col >> 1)] = h1;
            }
        }
    }
}

// ---------------- K4: BN statistics over out ----------------
__global__ __launch_bounds__(256) void k_stats(const float* __restrict__ out) {
    __shared__ float s_ps[8 * 128], s_pq[8 * 128];
    int tid = threadIdx.x;
    int tx = tid & 31, wp = tid >> 5;
    size_t idx = (size_t)blockIdx.x * 256 + tid;
    size_t stride = (size_t)gridDim.x * 256;   // multiple of 32 -> col group fixed
    const size_t n4 = (size_t)N_NODES * D / 4;
    const float4* o4 = reinterpret_cast<const float4*>(out);
    float ps[4] = {0, 0, 0, 0}, pq[4] = {0, 0, 0, 0};
    for (size_t i = idx; i < n4; i += stride) {
        float4 v = __ldg(&o4[i]);
        ps[0] += v.x; pq[0] += v.x * v.x;
        ps[1] += v.y; pq[1] += v.y * v.y;
        ps[2] += v.z; pq[2] += v.z * v.z;
        ps[3] += v.w; pq[3] += v.w * v.w;
    }
#pragma unroll
    for (int c = 0; c < 4; c++) {
        s_ps[wp * 128 + tx * 4 + c] = ps[c];
        s_pq[wp * 128 + tx * 4 + c] = pq[c];
    }
    __syncthreads();
    if (tid < 128) {
        float S = 0.f, Q = 0.f;
#pragma unroll
        for (int t = 0; t < 8; t++) { S += s_ps[t * 128 + tid]; Q += s_pq[t * 128 + tid]; }
        atomicAdd(&g_sum[tid], (double)S);
        atomicAdd(&g_sumsq[tid], (double)Q);
    }
}

// ---------------- K5: finalize BN affine ----------------
__global__ void k_finalize(const float* __restrict__ gamma, const float* __restrict__ beta) {
    int j = threadIdx.x;
    double mu = g_sum[j] / (double)N_NODES;
    double var = g_sumsq[j] / (double)N_NODES - mu * mu;
    float sc = gamma[j] * rsqrtf((float)var + BN_EPS);
    g_scale[j] = sc;
    g_shift[j] = beta[j] - (float)mu * sc;
}

// ---------------- K6: in-place normalize ----------------
__global__ void k_bn(float* __restrict__ out) {
    size_t idx = (size_t)blockIdx.x * blockDim.x + threadIdx.x;
    size_t stride = (size_t)gridDim.x * blockDim.x;
    const size_t n4 = (size_t)N_NODES * D / 4;
    float4* o4 = reinterpret_cast<float4*>(out);
    const float4* sc4 = reinterpret_cast<const float4*>(g_scale);
    const float4* sh4 = reinterpret_cast<const float4*>(g_shift);
    for (size_t i = idx; i < n4; i += stride) {
        float4 sc = sc4[i & 31];
        float4 sh = sh4[i & 31];
        float4 v = o4[i];
        v.x = fmaf(v.x, sc.x, sh.x);
        v.y = fmaf(v.y, sc.y, sh.y);
        v.z = fmaf(v.z, sc.z, sh.z);
        v.w = fmaf(v.w, sc.w, sh.w);
        o4[i] = v;
    }
}

// ---------------- launch ----------------
extern "C" void kernel_launch(void* const* d_in, const int* in_sizes, int n_in,
                              void* d_out, int out_size) {
    const float* node  = (const float*)d_in[0];
    const float* edge  = (const float*)d_in[1];
    const float* WO    = (const float*)d_in[2];
    const float* bO    = (const float*)d_in[3];
    const float* WI    = (const float*)d_in[4];
    const float* bI    = (const float*)d_in[5];
    const float* WS    = (const float*)d_in[6];
    const float* bS    = (const float*)d_in[7];
    const float* gamma = (const float*)d_in[8];
    const float* beta  = (const float*)d_in[9];
    const int*   src   = (const int*)d_in[10];
    const int*   dst   = (const int*)d_in[11];
    float* out = (float*)d_out;

    k_zero<<<1184, 256>>>();
    k_pack<<<49, 256>>>(WO, WI, WS, bO, bI, bS);
    k_scatter<<<N_EDGES / 8, 256>>>(node, edge, src, dst);
    k_gemm<<<(N_NODES + 127) / 128, 256>>>(node, out);
    k_stats<<<1184, 256>>>(out);
    k_finalize<<<1, 128>>>(gamma, beta);
    k_bn<<<2048, 256>>>(out);
}

// round 5
// speedup vs baseline: 2.4128x; 1.2514x over previous
#include <cuda_runtime.h>
#include <cuda_bf16.h>
#include <cuda_fp16.h>
#include <cstdint>
#include <cstddef>

#define N_NODES 100000
#define N_EDGES 600000
#define D 128
#define BN_EPS 1e-5f

// ---------------- scratch (static device globals; no allocation) ----------------
__device__ __half2 g_acc_o[(size_t)N_NODES * 64];   // fp16 sums of (h_src - e) at dst
__device__ __half2 g_acc_i[(size_t)N_NODES * 64];   // fp16 sums of (h_dst - e) at src
__device__ float  g_cnt[2 * N_NODES];               // [0:N) in-deg(dst), [N:2N) deg at src
// B fragments in mma order: [kstep 0..23][ntile 0..15][lane 0..31] = (b0h,b1h,b0l,b1l)
__device__ uint4  g_Bfrag[24 * 16 * 32];
__device__ float  g_bias[D];                        // b_O + b_I + b_S
__device__ double g_sum[D];
__device__ double g_sumsq[D];
__device__ float  g_scale[D];
__device__ float  g_shift[D];

// ---------------- helpers ----------------
__device__ __forceinline__ void red_add_h2v2(__half2* p, __half2 a, __half2 b) {
    asm volatile("red.global.add.noftz.v2.f16x2 [%0], {%1,%2};"
                 :: "l"(p), "r"(*reinterpret_cast<uint32_t*>(&a)),
                    "r"(*reinterpret_cast<uint32_t*>(&b)) : "memory");
}

__device__ __forceinline__ void mma16816(float* d, uint32_t a0, uint32_t a1, uint32_t a2,
                                         uint32_t a3, uint32_t b0, uint32_t b1) {
    asm volatile(
        "mma.sync.aligned.m16n8k16.row.col.f32.bf16.bf16.f32 "
        "{%0,%1,%2,%3}, {%4,%5,%6,%7}, {%8,%9}, {%0,%1,%2,%3};"
        : "+f"(d[0]), "+f"(d[1]), "+f"(d[2]), "+f"(d[3])
        : "r"(a0), "r"(a1), "r"(a2), "r"(a3), "r"(b0), "r"(b1));
}

// split scaled float2 into bf16x2 hi and lo words
__device__ __forceinline__ void split2(float2 v, float s, uint32_t& h, uint32_t& l) {
    float x = v.x * s, y = v.y * s;
    __nv_bfloat162 hp = __floats2bfloat162_rn(x, y);
    float hx = __low2float(hp), hy = __high2float(hp);
    __nv_bfloat162 lp = __floats2bfloat162_rn(x - hx, y - hy);
    h = *reinterpret_cast<uint32_t*>(&hp);
    l = *reinterpret_cast<uint32_t*>(&lp);
}

// ---------------- K0: zero scratch ----------------
__global__ void k_zero() {
    size_t idx = (size_t)blockIdx.x * blockDim.x + threadIdx.x;
    size_t stride = (size_t)gridDim.x * blockDim.x;
    const size_t n4 = (size_t)N_NODES * 16;   // uint4 per fp16 acc array
    uint4 z = make_uint4(0, 0, 0, 0);
    uint4* ao = reinterpret_cast<uint4*>(g_acc_o);
    uint4* ai = reinterpret_cast<uint4*>(g_acc_i);
    for (size_t i = idx; i < n4; i += stride) { ao[i] = z; ai[i] = z; }
    float4 zf = make_float4(0.f, 0.f, 0.f, 0.f);
    float4* cp = reinterpret_cast<float4*>(g_cnt);
    for (size_t i = idx; i < (2 * N_NODES) / 4; i += stride) cp[i] = zf;
    if (idx < D) { g_sum[idx] = 0.0; g_sumsq[idx] = 0.0; }
}

// ---------------- K1: pack W into bf16 hi/lo mma B-fragments + combined bias ----------------
__global__ void k_pack(const float* __restrict__ WO, const float* __restrict__ WI,
                       const float* __restrict__ WS, const float* __restrict__ bO,
                       const float* __restrict__ bI, const float* __restrict__ bS) {
    int idx = blockIdx.x * blockDim.x + threadIdx.x;
    if (idx < 24 * 16 * 32) {
        int t  = idx >> 9;          // kstep 0..23
        int nt = (idx >> 5) & 15;   // ntile 0..15
        int l  = idx & 31;          // lane
        int n  = nt * 8 + (l >> 2);           // output col
        int kg = t * 16 + (l & 3) * 2;        // global k of b0 first element
        const float* Wsrc = (kg < 128) ? WO : ((kg < 256) ? WI : WS);
        int kk = kg & 127;
        float w00 = __ldg(&Wsrc[n * 128 + kk]);
        float w01 = __ldg(&Wsrc[n * 128 + kk + 1]);
        float w10 = __ldg(&Wsrc[n * 128 + kk + 8]);
        float w11 = __ldg(&Wsrc[n * 128 + kk + 9]);
        uint32_t b0h, b0l, b1h, b1l;
        split2(make_float2(w00, w01), 1.f, b0h, b0l);
        split2(make_float2(w10, w11), 1.f, b1h, b1l);
        g_Bfrag[idx] = make_uint4(b0h, b1h, b0l, b1l);
    }
    if (idx < D) g_bias[idx] = bO[idx] + bI[idx] + bS[idx];
}

// ---------------- K2: edge scatter (one warp per edge, fp16 accumulators) ----------------
__global__ __launch_bounds__(256) void k_scatter(const float* __restrict__ node,
                                                 const float* __restrict__ edge,
                                                 const int* __restrict__ src,
                                                 const int* __restrict__ dst) {
    int e = blockIdx.x * 8 + (threadIdx.x >> 5);
    if (e >= N_EDGES) return;
    int lane = threadIdx.x & 31;
    int s = __ldg(&src[e]);
    int d = __ldg(&dst[e]);
    const float4* e4 = reinterpret_cast<const float4*>(edge);
    const float4* n4 = reinterpret_cast<const float4*>(node);
    float4 ee = __ldg(&e4[(size_t)e * 32 + lane]);
    float4 ns = __ldg(&n4[(size_t)s * 32 + lane]);
    float4 nd = __ldg(&n4[(size_t)d * 32 + lane]);
    __half2 mo01 = __floats2half2_rn(ns.x - ee.x, ns.y - ee.y);
    __half2 mo23 = __floats2half2_rn(ns.z - ee.z, ns.w - ee.w);
    __half2 mi01 = __floats2half2_rn(nd.x - ee.x, nd.y - ee.y);
    __half2 mi23 = __floats2half2_rn(nd.z - ee.z, nd.w - ee.w);
    red_add_h2v2(g_acc_o + (size_t)d * 64 + lane * 2, mo01, mo23);
    red_add_h2v2(g_acc_i + (size_t)s * 64 + lane * 2, mi01, mi23);
    if (lane == 0) {
        atomicAdd(&g_cnt[d], 1.f);
        atomicAdd(&g_cnt[N_NODES + s], 1.f);
    }
}

// ---------------- K3: bf16-split HMMA GEMM ----------------
// CTA: 128 rows x 128 cols, 8 warps = 4 (rows) x 2 (cols), warp tile 32x64.
__global__ __launch_bounds__(256, 2) void k_gemm(const float* __restrict__ node,
                                                 float* __restrict__ out) {
    __shared__ float s_inv[2 * 128];

    int tid = threadIdx.x;
    int l = tid & 31;
    int w = tid >> 5;
    int wy = w & 3;           // row group
    int wx = w >> 2;          // col group
    int row0 = blockIdx.x * 128;

    {
        int i = tid & 127;
        int r = row0 + i;
        float v = 0.f;
        if (r < N_NODES) v = 1.f / fmaxf(g_cnt[(tid < 128 ? 0 : N_NODES) + r], 1.f);
        s_inv[tid] = v;
    }
    __syncthreads();

    float acc[2][8][4];
#pragma unroll
    for (int mt = 0; mt < 2; mt++)
#pragma unroll
        for (int nt = 0; nt < 8; nt++)
#pragma unroll
            for (int q = 0; q < 4; q++) acc[mt][nt][q] = 0.f;

    const int lq = l >> 2;            // 0..7 row-within-tile group
    const int lk = (l & 3) * 2;       // k pair base within kstep

#pragma unroll 2
    for (int t = 0; t < 24; t++) {
        int k0 = t * 16;
        int sel = k0 >> 7;

        uint32_t aH[2][4], aL[2][4];
#pragma unroll
        for (int mt = 0; mt < 2; mt++) {
            int rl0 = wy * 32 + mt * 16 + lq;     // local rows
            int rl1 = rl0 + 8;
            int g0 = row0 + rl0, g1 = row0 + rl1;
            float2 p00, p01, p10, p11;
            float s0, s1;
            float2 zz = make_float2(0.f, 0.f);
            if (sel < 2) {
                const __half2* hb = (sel == 0) ? g_acc_o : g_acc_i;
                s0 = (sel == 0) ? s_inv[rl0] : s_inv[128 + rl0];
                s1 = (sel == 0) ? s_inv[rl1] : s_inv[128 + rl1];
                int i0 = ((k0 & 127) >> 1) + (lk >> 1);
                __half2 z2 = __float2half2_rn(0.f);
                __half2 q00 = (g0 < N_NODES) ? __ldg(&hb[(size_t)g0 * 64 + i0]) : z2;
                __half2 q01 = (g0 < N_NODES) ? __ldg(&hb[(size_t)g0 * 64 + i0 + 4]) : z2;
                __half2 q10 = (g1 < N_NODES) ? __ldg(&hb[(size_t)g1 * 64 + i0]) : z2;
                __half2 q11 = (g1 < N_NODES) ? __ldg(&hb[(size_t)g1 * 64 + i0 + 4]) : z2;
                p00 = __half22float2(q00); p01 = __half22float2(q01);
                p10 = __half22float2(q10); p11 = __half22float2(q11);
            } else {
                s0 = 1.f; s1 = 1.f;
                const float2* b2 = reinterpret_cast<const float2*>(node);
                int i0 = (((k0 & 127) + lk) >> 1);
                p00 = (g0 < N_NODES) ? __ldg(&b2[(size_t)g0 * 64 + i0]) : zz;
                p01 = (g0 < N_NODES) ? __ldg(&b2[(size_t)g0 * 64 + i0 + 4]) : zz;
                p10 = (g1 < N_NODES) ? __ldg(&b2[(size_t)g1 * 64 + i0]) : zz;
                p11 = (g1 < N_NODES) ? __ldg(&b2[(size_t)g1 * 64 + i0 + 4]) : zz;
            }
            split2(p00, s0, aH[mt][0], aL[mt][0]);
            split2(p10, s1, aH[mt][1], aL[mt][1]);
            split2(p01, s0, aH[mt][2], aL[mt][2]);
            split2(p11, s1, aH[mt][3], aL[mt][3]);
        }

#pragma unroll
        for (int nt = 0; nt < 8; nt++) {
            uint4 B = __ldg(&g_Bfrag[((t * 16) + (wx * 8 + nt)) * 32 + l]);
#pragma unroll
            for (int mt = 0; mt < 2; mt++) {
                mma16816(acc[mt][nt], aH[mt][0], aH[mt][1], aH[mt][2], aH[mt][3], B.x, B.y);
                mma16816(acc[mt][nt], aH[mt][0], aH[mt][1], aH[mt][2], aH[mt][3], B.z, B.w);
                mma16816(acc[mt][nt], aL[mt][0], aL[mt][1], aL[mt][2], aL[mt][3], B.x, B.y);
            }
        }
    }

    // ---- epilogue: h = (acc + bias)/3 ----
    const float third = 1.f / 3.f;
    const float2* bias2 = reinterpret_cast<const float2*>(g_bias);
    float2* o2 = reinterpret_cast<float2*>(out);
#pragma unroll
    for (int mt = 0; mt < 2; mt++) {
        int ra = row0 + wy * 32 + mt * 16 + lq;
        int rb = ra + 8;
#pragma unroll
        for (int nt = 0; nt < 8; nt++) {
            int col = wx * 64 + nt * 8 + lk;
            float2 bv = __ldg(&bias2[col >> 1]);
            if (ra < N_NODES) {
                float2 h0;
                h0.x = (acc[mt][nt][0] + bv.x) * third;
                h0.y = (acc[mt][nt][1] + bv.y) * third;
                o2[(size_t)ra * 64 + (col >> 1)] = h0;
            }
            if (rb < N_NODES) {
                float2 h1;
                h1.x = (acc[mt][nt][2] + bv.x) * third;
                h1.y = (acc[mt][nt][3] + bv.y) * third;
                o2[(size_t)rb * 64 + (col >> 1)] = h1;
            }
        }
    }
}

// ---------------- K4: BN statistics over out ----------------
__global__ __launch_bounds__(256) void k_stats(const float* __restrict__ out) {
    __shared__ float s_ps[8 * 128], s_pq[8 * 128];
    int tid = threadIdx.x;
    int tx = tid & 31, wp = tid >> 5;
    size_t idx = (size_t)blockIdx.x * 256 + tid;
    size_t stride = (size_t)gridDim.x * 256;
    const size_t n4 = (size_t)N_NODES * D / 4;
    const float4* o4 = reinterpret_cast<const float4*>(out);
    float ps[4] = {0, 0, 0, 0}, pq[4] = {0, 0, 0, 0};
    for (size_t i = idx; i < n4; i += stride) {
        float4 v = __ldg(&o4[i]);
        ps[0] += v.x; pq[0] += v.x * v.x;
        ps[1] += v.y; pq[1] += v.y * v.y;
        ps[2] += v.z; pq[2] += v.z * v.z;
        ps[3] += v.w; pq[3] += v.w * v.w;
    }
#pragma unroll
    for (int c = 0; c < 4; c++) {
        s_ps[wp * 128 + tx * 4 + c] = ps[c];
        s_pq[wp * 128 + tx * 4 + c] = pq[c];
    }
    __syncthreads();
    if (tid < 128) {
        float S = 0.f, Q = 0.f;
#pragma unroll
        for (int t = 0; t < 8; t++) { S += s_ps[t * 128 + tid]; Q += s_pq[t * 128 + tid]; }
        atomicAdd(&g_sum[tid], (double)S);
        atomicAdd(&g_sumsq[tid], (double)Q);
    }
}

// ---------------- K5: finalize BN affine ----------------
__global__ void k_finalize(const float* __restrict__ gamma, const float* __restrict__ beta) {
    int j = threadIdx.x;
    double mu = g_sum[j] / (double)N_NODES;
    double var = g_sumsq[j] / (double)N_NODES - mu * mu;
    float sc = gamma[j] * rsqrtf((float)var + BN_EPS);
    g_scale[j] = sc;
    g_shift[j] = beta[j] - (float)mu * sc;
}

// ---------------- K6: in-place normalize ----------------
__global__ void k_bn(float* __restrict__ out) {
    size_t idx = (size_t)blockIdx.x * blockDim.x + threadIdx.x;
    size_t stride = (size_t)gridDim.x * blockDim.x;
    const size_t n4 = (size_t)N_NODES * D / 4;
    float4* o4 = reinterpret_cast<float4*>(out);
    const float4* sc4 = reinterpret_cast<const float4*>(g_scale);
    const float4* sh4 = reinterpret_cast<const float4*>(g_shift);
    for (size_t i = idx; i < n4; i += stride) {
        float4 sc = sc4[i & 31];
        float4 sh = sh4[i & 31];
        float4 v = o4[i];
        v.x = fmaf(v.x, sc.x, sh.x);
        v.y = fmaf(v.y, sc.y, sh.y);
        v.z = fmaf(v.z, sc.z, sh.z);
        v.w = fmaf(v.w, sc.w, sh.w);
        o4[i] = v;
    }
}

// ---------------- launch ----------------
extern "C" void kernel_launch(void* const* d_in, const int* in_sizes, int n_in,
                              void* d_out, int out_size) {
    const float* node  = (const float*)d_in[0];
    const float* edge  = (const float*)d_in[1];
    const float* WO    = (const float*)d_in[2];
    const float* bO    = (const float*)d_in[3];
    const float* WI    = (const float*)d_in[4];
    const float* bI    = (const float*)d_in[5];
    const float* WS    = (const float*)d_in[6];
    const float* bS    = (const float*)d_in[7];
    const float* gamma = (const float*)d_in[8];
    const float* beta  = (const float*)d_in[9];
    const int*   src   = (const int*)d_in[10];
    const int*   dst   = (const int*)d_in[11];
    float* out = (float*)d_out;

    k_zero<<<1184, 256>>>();
    k_pack<<<49, 256>>>(WO, WI, WS, bO, bI, bS);
    k_scatter<<<N_EDGES / 8, 256>>>(node, edge, src, dst);
    k_gemm<<<(N_NODES + 127) / 128, 256>>>(node, out);
    k_stats<<<1184, 256>>>(out);
    k_finalize<<<1, 128>>>(gamma, beta);
    k_bn<<<2048, 256>>>(out);
}

// round 6
// speedup vs baseline: 2.7622x; 1.1448x over previous
#include <cuda_runtime.h>
#include <cuda_bf16.h>
#include <cuda_fp16.h>
#include <cstdint>
#include <cstddef>

#define N_NODES 100000
#define N_EDGES 600000
#define D 128
#define BN_EPS 1e-5f

// ---------------- scratch (static device globals; no allocation) ----------------
__device__ __half2 g_acc_o[(size_t)N_NODES * 64];   // fp16 sums of (h_src - e) at dst
__device__ __half2 g_acc_i[(size_t)N_NODES * 64];   // fp16 sums of (h_dst - e) at src
__device__ float  g_cnt[2 * N_NODES];               // [0:N) in-deg(dst), [N:2N) deg at src
// B fragments in mma order: [kstep 0..23][ntile 0..15][lane 0..31] = (b0h,b1h,b0l,b1l)
// ksteps 0..15: fp16 hi/lo split;  ksteps 16..23: bf16 hi/lo split
__device__ uint4  g_Bfrag[24 * 16 * 32];
__device__ float  g_bias[D];                        // b_O + b_I + b_S
__device__ double g_sum[D];
__device__ double g_sumsq[D];
__device__ float  g_scale[D];
__device__ float  g_shift[D];

// ---------------- helpers ----------------
__device__ __forceinline__ void red_add_h2v4(__half2* p, __half2 a, __half2 b,
                                             __half2 c, __half2 d) {
    asm volatile("red.global.add.noftz.v4.f16x2 [%0], {%1,%2,%3,%4};"
                 :: "l"(p),
                    "r"(*reinterpret_cast<uint32_t*>(&a)),
                    "r"(*reinterpret_cast<uint32_t*>(&b)),
                    "r"(*reinterpret_cast<uint32_t*>(&c)),
                    "r"(*reinterpret_cast<uint32_t*>(&d)) : "memory");
}

__device__ __forceinline__ void mma_bf(float* d, uint32_t a0, uint32_t a1, uint32_t a2,
                                       uint32_t a3, uint32_t b0, uint32_t b1) {
    asm volatile(
        "mma.sync.aligned.m16n8k16.row.col.f32.bf16.bf16.f32 "
        "{%0,%1,%2,%3}, {%4,%5,%6,%7}, {%8,%9}, {%0,%1,%2,%3};"
        : "+f"(d[0]), "+f"(d[1]), "+f"(d[2]), "+f"(d[3])
        : "r"(a0), "r"(a1), "r"(a2), "r"(a3), "r"(b0), "r"(b1));
}

__device__ __forceinline__ void mma_fp16(float* d, uint32_t a0, uint32_t a1, uint32_t a2,
                                         uint32_t a3, uint32_t b0, uint32_t b1) {
    asm volatile(
        "mma.sync.aligned.m16n8k16.row.col.f32.f16.f16.f32 "
        "{%0,%1,%2,%3}, {%4,%5,%6,%7}, {%8,%9}, {%0,%1,%2,%3};"
        : "+f"(d[0]), "+f"(d[1]), "+f"(d[2]), "+f"(d[3])
        : "r"(a0), "r"(a1), "r"(a2), "r"(a3), "r"(b0), "r"(b1));
}

// split float2 into bf16x2 hi and lo words
__device__ __forceinline__ void split2(float2 v, float s, uint32_t& h, uint32_t& l) {
    float x = v.x * s, y = v.y * s;
    __nv_bfloat162 hp = __floats2bfloat162_rn(x, y);
    float hx = __low2float(hp), hy = __high2float(hp);
    __nv_bfloat162 lp = __floats2bfloat162_rn(x - hx, y - hy);
    h = *reinterpret_cast<uint32_t*>(&hp);
    l = *reinterpret_cast<uint32_t*>(&lp);
}

// split float2 into fp16x2 hi and lo words
__device__ __forceinline__ void split2h(float2 v, uint32_t& h, uint32_t& l) {
    __half2 hp = __floats2half2_rn(v.x, v.y);
    float hx = __low2float(hp), hy = __high2float(hp);
    __half2 lp = __floats2half2_rn(v.x - hx, v.y - hy);
    h = *reinterpret_cast<uint32_t*>(&hp);
    l = *reinterpret_cast<uint32_t*>(&lp);
}

// ---------------- K0: zero scratch ----------------
__global__ void k_zero() {
    size_t idx = (size_t)blockIdx.x * blockDim.x + threadIdx.x;
    size_t stride = (size_t)gridDim.x * blockDim.x;
    const size_t n4 = (size_t)N_NODES * 16;   // uint4 per fp16 acc array
    uint4 z = make_uint4(0, 0, 0, 0);
    uint4* ao = reinterpret_cast<uint4*>(g_acc_o);
    uint4* ai = reinterpret_cast<uint4*>(g_acc_i);
    for (size_t i = idx; i < n4; i += stride) { ao[i] = z; ai[i] = z; }
    float4 zf = make_float4(0.f, 0.f, 0.f, 0.f);
    float4* cp = reinterpret_cast<float4*>(g_cnt);
    for (size_t i = idx; i < (2 * N_NODES) / 4; i += stride) cp[i] = zf;
    if (idx < D) { g_sum[idx] = 0.0; g_sumsq[idx] = 0.0; }
}

// ---------------- K1: pack W into mma B-fragments + combined bias ----------------
__global__ void k_pack(const float* __restrict__ WO, const float* __restrict__ WI,
                       const float* __restrict__ WS, const float* __restrict__ bO,
                       const float* __restrict__ bI, const float* __restrict__ bS) {
    int idx = blockIdx.x * blockDim.x + threadIdx.x;
    if (idx < 24 * 16 * 32) {
        int t  = idx >> 9;          // kstep 0..23
        int nt = (idx >> 5) & 15;   // ntile 0..15
        int l  = idx & 31;          // lane
        int n  = nt * 8 + (l >> 2);           // output col
        int kg = t * 16 + (l & 3) * 2;        // global k of b0 first element
        const float* Wsrc = (kg < 128) ? WO : ((kg < 256) ? WI : WS);
        int kk = kg & 127;
        float w00 = __ldg(&Wsrc[n * 128 + kk]);
        float w01 = __ldg(&Wsrc[n * 128 + kk + 1]);
        float w10 = __ldg(&Wsrc[n * 128 + kk + 8]);
        float w11 = __ldg(&Wsrc[n * 128 + kk + 9]);
        uint32_t b0h, b0l, b1h, b1l;
        if (t < 16) {
            split2h(make_float2(w00, w01), b0h, b0l);
            split2h(make_float2(w10, w11), b1h, b1l);
        } else {
            split2(make_float2(w00, w01), 1.f, b0h, b0l);
            split2(make_float2(w10, w11), 1.f, b1h, b1l);
        }
        g_Bfrag[idx] = make_uint4(b0h, b1h, b0l, b1l);
    }
    if (idx < D) g_bias[idx] = bO[idx] + bI[idx] + bS[idx];
}

// ---------------- K2: edge scatter (half-warp split, v4.f16x2 RED) ----------------
__global__ __launch_bounds__(256) void k_scatter(const float* __restrict__ node,
                                                 const float* __restrict__ edge,
                                                 const int* __restrict__ src,
                                                 const int* __restrict__ dst) {
    int e = blockIdx.x * 8 + (threadIdx.x >> 5);
    if (e >= N_EDGES) return;
    int lane = threadIdx.x & 31;
    int half = lane >> 4;
    int i = lane & 15;
    int s = __ldg(&src[e]);
    int d = __ldg(&dst[e]);
    const float4* e4 = reinterpret_cast<const float4*>(edge);
    const float4* n4 = reinterpret_cast<const float4*>(node);
    // each lane loads one float4 of the edge row; redistribute so lane gets 2i, 2i+1
    float4 ee = __ldg(&e4[(size_t)e * 32 + lane]);
    float4 eA, eB;
    eA.x = __shfl_sync(0xFFFFFFFFu, ee.x, 2 * i);
    eA.y = __shfl_sync(0xFFFFFFFFu, ee.y, 2 * i);
    eA.z = __shfl_sync(0xFFFFFFFFu, ee.z, 2 * i);
    eA.w = __shfl_sync(0xFFFFFFFFu, ee.w, 2 * i);
    eB.x = __shfl_sync(0xFFFFFFFFu, ee.x, 2 * i + 1);
    eB.y = __shfl_sync(0xFFFFFFFFu, ee.y, 2 * i + 1);
    eB.z = __shfl_sync(0xFFFFFFFFu, ee.z, 2 * i + 1);
    eB.w = __shfl_sync(0xFFFFFFFFu, ee.w, 2 * i + 1);
    // half 0: message (node[s] - e) -> acc_o row d ; half 1: (node[d] - e) -> acc_i row s
    int nrow = half ? d : s;
    const float4* np = n4 + (size_t)nrow * 32;
    float4 nA = __ldg(&np[2 * i]);
    float4 nB = __ldg(&np[2 * i + 1]);
    __half2 m0 = __floats2half2_rn(nA.x - eA.x, nA.y - eA.y);
    __half2 m1 = __floats2half2_rn(nA.z - eA.z, nA.w - eA.w);
    __half2 m2 = __floats2half2_rn(nB.x - eB.x, nB.y - eB.y);
    __half2 m3 = __floats2half2_rn(nB.z - eB.z, nB.w - eB.w);
    __half2* base = half ? (g_acc_i + (size_t)s * 64) : (g_acc_o + (size_t)d * 64);
    red_add_h2v4(base + i * 4, m0, m1, m2, m3);
    if (lane == 0)  atomicAdd(&g_cnt[d], 1.f);
    if (lane == 16) atomicAdd(&g_cnt[N_NODES + s], 1.f);
}

// ---------------- K3: mixed fp16/bf16 HMMA GEMM + fused BN stats ----------------
// CTA: 128 rows x 128 cols, 8 warps = 4 (rows) x 2 (cols), warp tile 32x64.
__global__ __launch_bounds__(256, 2) void k_gemm(const float* __restrict__ node,
                                                 float* __restrict__ out) {
    __shared__ float s_inv[2 * 128];
    __shared__ float s_red[2 * 128];   // [0:128) col sums, [128:256) col sumsq

    int tid = threadIdx.x;
    int l = tid & 31;
    int w = tid >> 5;
    int wy = w & 3;           // row group
    int wx = w >> 2;          // col group
    int row0 = blockIdx.x * 128;

    {
        int i = tid & 127;
        int r = row0 + i;
        float v = 0.f;
        if (r < N_NODES) v = 1.f / fmaxf(g_cnt[(tid < 128 ? 0 : N_NODES) + r], 1.f);
        s_inv[tid] = v;
        s_red[tid] = 0.f;
    }
    __syncthreads();

    float acc[2][8][4];
#pragma unroll
    for (int mt = 0; mt < 2; mt++)
#pragma unroll
        for (int nt = 0; nt < 8; nt++)
#pragma unroll
            for (int q = 0; q < 4; q++) acc[mt][nt][q] = 0.f;

    const int lq = l >> 2;            // 0..7 row-within-tile group
    const int lk = (l & 3) * 2;       // k pair base within kstep

    // ---- fp16 chunks: t = 0..15 (acc_o for t<8, acc_i for t>=8), A exact fp16 ----
#pragma unroll 2
    for (int t = 0; t < 16; t++) {
        int sel = t >> 3;
        const __half2* hb = (sel == 0) ? g_acc_o : g_acc_i;
        int i0 = (t & 7) * 8 + (lk >> 1);

        uint32_t A[2][4];
#pragma unroll
        for (int mt = 0; mt < 2; mt++) {
            int rl0 = wy * 32 + mt * 16 + lq;
            int rl1 = rl0 + 8;
            int g0 = row0 + rl0, g1 = row0 + rl1;
            float s0 = (sel == 0) ? s_inv[rl0] : s_inv[128 + rl0];
            float s1 = (sel == 0) ? s_inv[rl1] : s_inv[128 + rl1];
            __half2 h0 = __float2half2_rn(s0);
            __half2 h1 = __float2half2_rn(s1);
            __half2 z2 = __float2half2_rn(0.f);
            __half2 q0 = (g0 < N_NODES) ? __hmul2(__ldg(&hb[(size_t)g0 * 64 + i0]), h0) : z2;
            __half2 q1 = (g1 < N_NODES) ? __hmul2(__ldg(&hb[(size_t)g1 * 64 + i0]), h1) : z2;
            __half2 q2 = (g0 < N_NODES) ? __hmul2(__ldg(&hb[(size_t)g0 * 64 + i0 + 4]), h0) : z2;
            __half2 q3 = (g1 < N_NODES) ? __hmul2(__ldg(&hb[(size_t)g1 * 64 + i0 + 4]), h1) : z2;
            A[mt][0] = *reinterpret_cast<uint32_t*>(&q0);
            A[mt][1] = *reinterpret_cast<uint32_t*>(&q1);
            A[mt][2] = *reinterpret_cast<uint32_t*>(&q2);
            A[mt][3] = *reinterpret_cast<uint32_t*>(&q3);
        }
#pragma unroll
        for (int nt = 0; nt < 8; nt++) {
            uint4 B = __ldg(&g_Bfrag[((t * 16) + (wx * 8 + nt)) * 32 + l]);
#pragma unroll
            for (int mt = 0; mt < 2; mt++) {
                mma_fp16(acc[mt][nt], A[mt][0], A[mt][1], A[mt][2], A[mt][3], B.x, B.y);
                mma_fp16(acc[mt][nt], A[mt][0], A[mt][1], A[mt][2], A[mt][3], B.z, B.w);
            }
        }
    }

    // ---- bf16 chunks: t = 16..23 (node embeddings, fp32 -> bf16 split) ----
#pragma unroll 2
    for (int t = 16; t < 24; t++) {
        int koff = ((t - 16) * 16 + lk) >> 1;   // float2 index within row
        uint32_t aH[2][4], aL[2][4];
#pragma unroll
        for (int mt = 0; mt < 2; mt++) {
            int rl0 = wy * 32 + mt * 16 + lq;
            int rl1 = rl0 + 8;
            int g0 = row0 + rl0, g1 = row0 + rl1;
            const float2* b2 = reinterpret_cast<const float2*>(node);
            float2 zz = make_float2(0.f, 0.f);
            float2 p00 = (g0 < N_NODES) ? __ldg(&b2[(size_t)g0 * 64 + koff]) : zz;
            float2 p01 = (g0 < N_NODES) ? __ldg(&b2[(size_t)g0 * 64 + koff + 4]) : zz;
            float2 p10 = (g1 < N_NODES) ? __ldg(&b2[(size_t)g1 * 64 + koff]) : zz;
            float2 p11 = (g1 < N_NODES) ? __ldg(&b2[(size_t)g1 * 64 + koff + 4]) : zz;
            split2(p00, 1.f, aH[mt][0], aL[mt][0]);
            split2(p10, 1.f, aH[mt][1], aL[mt][1]);
            split2(p01, 1.f, aH[mt][2], aL[mt][2]);
            split2(p11, 1.f, aH[mt][3], aL[mt][3]);
        }
#pragma unroll
        for (int nt = 0; nt < 8; nt++) {
            uint4 B = __ldg(&g_Bfrag[((t * 16) + (wx * 8 + nt)) * 32 + l]);
#pragma unroll
            for (int mt = 0; mt < 2; mt++) {
                mma_bf(acc[mt][nt], aH[mt][0], aH[mt][1], aH[mt][2], aH[mt][3], B.x, B.y);
                mma_bf(acc[mt][nt], aH[mt][0], aH[mt][1], aH[mt][2], aH[mt][3], B.z, B.w);
                mma_bf(acc[mt][nt], aL[mt][0], aL[mt][1], aL[mt][2], aL[mt][3], B.x, B.y);
            }
        }
    }

    // ---- epilogue: h = (acc + bias)/3, store, BN partial stats ----
    const float third = 1.f / 3.f;
    const float2* bias2 = reinterpret_cast<const float2*>(g_bias);
    float2* o2 = reinterpret_cast<float2*>(out);
    float ps[16], pq[16];
#pragma unroll
    for (int j = 0; j < 16; j++) { ps[j] = 0.f; pq[j] = 0.f; }

#pragma unroll
    for (int mt = 0; mt < 2; mt++) {
        int ra = row0 + wy * 32 + mt * 16 + lq;
        int rb = ra + 8;
#pragma unroll
        for (int nt = 0; nt < 8; nt++) {
            int col = wx * 64 + nt * 8 + lk;
            float2 bv = __ldg(&bias2[col >> 1]);
            if (ra < N_NODES) {
                float2 h0;
                h0.x = (acc[mt][nt][0] + bv.x) * third;
                h0.y = (acc[mt][nt][1] + bv.y) * third;
                o2[(size_t)ra * 64 + (col >> 1)] = h0;
                ps[nt * 2 + 0] += h0.x; pq[nt * 2 + 0] += h0.x * h0.x;
                ps[nt * 2 + 1] += h0.y; pq[nt * 2 + 1] += h0.y * h0.y;
            }
            if (rb < N_NODES) {
                float2 h1;
                h1.x = (acc[mt][nt][2] + bv.x) * third;
                h1.y = (acc[mt][nt][3] + bv.y) * third;
                o2[(size_t)rb * 64 + (col >> 1)] = h1;
                ps[nt * 2 + 0] += h1.x; pq[nt * 2 + 0] += h1.x * h1.x;
                ps[nt * 2 + 1] += h1.y; pq[nt * 2 + 1] += h1.y * h1.y;
            }
        }
    }
    // reduce across the 8 lq row-groups (lanes differing in bits 2,3,4)
#pragma unroll
    for (int j = 0; j < 16; j++) {
        ps[j] += __shfl_xor_sync(0xFFFFFFFFu, ps[j], 4);
        ps[j] += __shfl_xor_sync(0xFFFFFFFFu, ps[j], 8);
        ps[j] += __shfl_xor_sync(0xFFFFFFFFu, ps[j], 16);
        pq[j] += __shfl_xor_sync(0xFFFFFFFFu, pq[j], 4);
        pq[j] += __shfl_xor_sync(0xFFFFFFFFu, pq[j], 8);
        pq[j] += __shfl_xor_sync(0xFFFFFFFFu, pq[j], 16);
    }
    if (l < 4) {
#pragma unroll
        for (int j = 0; j < 16; j++) {
            int col = wx * 64 + (j >> 1) * 8 + l * 2 + (j & 1);
            atomicAdd(&s_red[col], ps[j]);
            atomicAdd(&s_red[128 + col], pq[j]);
        }
    }
    __syncthreads();
    if (tid < 128) atomicAdd(&g_sum[tid], (double)s_red[tid]);
    else           atomicAdd(&g_sumsq[tid - 128], (double)s_red[tid]);
}

// ---------------- K4: finalize BN affine ----------------
__global__ void k_finalize(const float* __restrict__ gamma, const float* __restrict__ beta) {
    int j = threadIdx.x;
    double mu = g_sum[j] / (double)N_NODES;
    double var = g_sumsq[j] / (double)N_NODES - mu * mu;
    float sc = gamma[j] * rsqrtf((float)var + BN_EPS);
    g_scale[j] = sc;
    g_shift[j] = beta[j] - (float)mu * sc;
}

// ---------------- K5: in-place normalize ----------------
__global__ void k_bn(float* __restrict__ out) {
    size_t idx = (size_t)blockIdx.x * blockDim.x + threadIdx.x;
    size_t stride = (size_t)gridDim.x * blockDim.x;
    const size_t n4 = (size_t)N_NODES * D / 4;
    float4* o4 = reinterpret_cast<float4*>(out);
    const float4* sc4 = reinterpret_cast<const float4*>(g_scale);
    const float4* sh4 = reinterpret_cast<const float4*>(g_shift);
    for (size_t i = idx; i < n4; i += stride) {
        float4 sc = sc4[i & 31];
        float4 sh = sh4[i & 31];
        float4 v = o4[i];
        v.x = fmaf(v.x, sc.x, sh.x);
        v.y = fmaf(v.y, sc.y, sh.y);
        v.z = fmaf(v.z, sc.z, sh.z);
        v.w = fmaf(v.w, sc.w, sh.w);
        o4[i] = v;
    }
}

// ---------------- launch ----------------
extern "C" void kernel_launch(void* const* d_in, const int* in_sizes, int n_in,
                              void* d_out, int out_size) {
    const float* node  = (const float*)d_in[0];
    const float* edge  = (const float*)d_in[1];
    const float* WO    = (const float*)d_in[2];
    const float* bO    = (const float*)d_in[3];
    const float* WI    = (const float*)d_in[4];
    const float* bI    = (const float*)d_in[5];
    const float* WS    = (const float*)d_in[6];
    const float* bS    = (const float*)d_in[7];
    const float* gamma = (const float*)d_in[8];
    const float* beta  = (const float*)d_in[9];
    const int*   src   = (const int*)d_in[10];
    const int*   dst   = (const int*)d_in[11];
    float* out = (float*)d_out;

    k_zero<<<1184, 256>>>();
    k_pack<<<49, 256>>>(WO, WI, WS, bO, bI, bS);
    k_scatter<<<N_EDGES / 8, 256>>>(node, edge, src, dst);
    k_gemm<<<(N_NODES + 127) / 128, 256>>>(node, out);
    k_finalize<<<1, 128>>>(gamma, beta);
    k_bn<<<2048, 256>>>(out);
}